// round 7
// baseline (speedup 1.0000x reference)
#include <cuda_runtime.h>
#include <cstdint>

#define MDIM 12288
#define CIN 8
#define NPAIR 4           // channel pairs (CIN/2)
#define COUT 16
#define KTAP 5
#define TJ 512            // j-tile staged in smem
#define RPW 4             // rows of L per warp
#define NW 8              // warps per block
#define RPB (RPW * NW)    // 32 rows per block
#define NBLOCKS (MDIM / RPB)  // 384
#define NTILES (MDIM / TJ)    // 24
#define TOT (NTILES * 4)      // 96 flattened (tile, s) iterations

// 128B-row swizzle: XOR bits[7:10) into [4:7). Keeps >=8B alignment.
#define SWZ(b) ((b) ^ (((b) >> 3) & 0x70))

// Scratch panels for L^1 x .. L^4 x, each [CIN][MDIM].
__device__ __align__(16) float g_pan[KTAP - 1][CIN * MDIM];

__device__ __forceinline__ unsigned long long pack2(float lo, float hi) {
    unsigned long long r;
    asm("mov.b64 %0, {%1, %2};" : "=l"(r) : "f"(lo), "f"(hi));
    return r;
}
__device__ __forceinline__ void unpack2(unsigned long long v, float& lo, float& hi) {
    asm("mov.b64 {%0, %1}, %2;" : "=f"(lo), "=f"(hi) : "l"(v));
}
__device__ __forceinline__ void fma2(unsigned long long& acc,
                                     unsigned long long a, unsigned long long b) {
    asm("fma.rn.f32x2 %0, %1, %2, %0;" : "+l"(acc) : "l"(a), "l"(b));
}

// next[i][m] = sum_j L[m][j] * cur[i][j], channels packed in f32x2 pairs.
// Software-pipelined: L loads for iteration T+1 issue before computing T.
__global__ __launch_bounds__(256, 2)
void step_kernel(const float* __restrict__ L,
                 const float* __restrict__ cur,
                 float* __restrict__ nxt) {
    __shared__ __align__(16) unsigned char sp[TJ * NPAIR * 8];   // 16 KB

    const int tid  = threadIdx.x;
    const int lane = tid & 31;
    const int w    = tid >> 5;
    const int m0   = blockIdx.x * RPB + w * RPW;

    unsigned long long acc[RPW][NPAIR];
#pragma unroll
    for (int r = 0; r < RPW; ++r)
#pragma unroll
        for (int p = 0; p < NPAIR; ++p) acc[r][p] = 0ull;

    float4 aA[RPW], aB[RPW];

    // Prologue: issue loads for T=0 (tile 0, s=0).
#pragma unroll
    for (int r = 0; r < RPW; ++r)
        aA[r] = __ldcs(reinterpret_cast<const float4*>(
                    L + (size_t)(m0 + r) * MDIM) + lane);

    auto body = [&](int T, float4 (&ause)[RPW], float4 (&anxt)[RPW]) {
        const int s_  = T & 3;
        const int jb_ = (T >> 2) * TJ;

        if (s_ == 0) {
            // All warps done reading previous tile's panel before overwrite.
            __syncthreads();
#pragma unroll
            for (int it = 0; it < 8; ++it) {
                int idx = it * 256 + tid;
                int j   = idx & (TJ - 1);
                int p   = idx >> 9;                       // 0..3
                unsigned long long v =
                    pack2(cur[(size_t)(2 * p) * MDIM + jb_ + j],
                          cur[(size_t)(2 * p + 1) * MDIM + jb_ + j]);
                *reinterpret_cast<unsigned long long*>(sp + SWZ(j * 32 + p * 8)) = v;
            }
            __syncthreads();
        }

        // Issue next iteration's L loads (lands while we compute this one).
        if (T + 1 < TOT) {
            const int t1  = T + 1;
            const int jb1 = (t1 >> 2) * TJ;
            const int c1  = (t1 & 3) * 32 + lane;
#pragma unroll
            for (int r = 0; r < RPW; ++r)
                anxt[r] = __ldcs(reinterpret_cast<const float4*>(
                              L + (size_t)(m0 + r) * MDIM + jb1) + c1);
        }

        // Compute iteration T with already-landed ause.
        const int c = s_ * 32 + lane;
#pragma unroll
        for (int jj = 0; jj < 4; ++jj) {
            const int jl = 4 * c + jj;                    // tile-local column
            ulonglong2 q0 = *reinterpret_cast<const ulonglong2*>(sp + SWZ(jl * 32));
            ulonglong2 q1 = *reinterpret_cast<const ulonglong2*>(sp + SWZ(jl * 32 + 16));
#pragma unroll
            for (int r = 0; r < RPW; ++r) {
                float av = (jj == 0) ? ause[r].x : (jj == 1) ? ause[r].y
                         : (jj == 2) ? ause[r].z : ause[r].w;
                unsigned long long aa = pack2(av, av);
                fma2(acc[r][0], aa, q0.x);
                fma2(acc[r][1], aa, q0.y);
                fma2(acc[r][2], aa, q1.x);
                fma2(acc[r][3], aa, q1.y);
            }
        }
    };

    for (int T = 0; T < TOT; T += 2) {      // TOT even: register ping-pong
        body(T,     aA, aB);
        body(T + 1, aB, aA);
    }

    // Warp reduction over lanes (disjoint j), then store.
#pragma unroll
    for (int r = 0; r < RPW; ++r)
#pragma unroll
        for (int p = 0; p < NPAIR; ++p) {
            float v0, v1;
            unpack2(acc[r][p], v0, v1);
#pragma unroll
            for (int d = 16; d > 0; d >>= 1) {
                v0 += __shfl_down_sync(0xffffffffu, v0, d);
                v1 += __shfl_down_sync(0xffffffffu, v1, d);
            }
            if (lane == 0) {
                nxt[(size_t)(2 * p) * MDIM + m0 + r]     = v0;
                nxt[(size_t)(2 * p + 1) * MDIM + m0 + r] = v1;
            }
        }
}

// y[o][m] = bias[o] + sum_{i,k} theta[o][i][k] * P[k][i][m]
__global__ __launch_bounds__(256)
void mix_kernel(const float* __restrict__ x,
                const float* __restrict__ theta,
                const float* __restrict__ bias,
                float* __restrict__ out) {
    __shared__ float th[COUT * CIN * KTAP];
    __shared__ float bs[COUT];
    const int tid = threadIdx.x;
    for (int idx = tid; idx < COUT * CIN * KTAP; idx += blockDim.x)
        th[idx] = theta[idx];
    if (tid < COUT) bs[tid] = bias[tid];
    __syncthreads();

    const int m = blockIdx.x * blockDim.x + tid;
    if (m >= MDIM) return;

    float p[KTAP][CIN];
#pragma unroll
    for (int i = 0; i < CIN; ++i) p[0][i] = x[(size_t)i * MDIM + m];
#pragma unroll
    for (int k = 1; k < KTAP; ++k)
#pragma unroll
        for (int i = 0; i < CIN; ++i)
            p[k][i] = g_pan[k - 1][i * MDIM + m];

#pragma unroll
    for (int o = 0; o < COUT; ++o) {
        float s = bs[o];
#pragma unroll
        for (int i = 0; i < CIN; ++i)
#pragma unroll
            for (int k = 0; k < KTAP; ++k)
                s += th[(o * CIN + i) * KTAP + k] * p[k][i];
        out[(size_t)o * MDIM + m] = s;
    }
}

extern "C" void kernel_launch(void* const* d_in, const int* in_sizes, int n_in,
                              void* d_out, int out_size) {
    const float* L     = (const float*)d_in[0];
    const float* x     = (const float*)d_in[1];
    const float* theta = (const float*)d_in[2];
    const float* bias  = (const float*)d_in[3];
    float* out = (float*)d_out;

    float* pan = nullptr;
    cudaGetSymbolAddress((void**)&pan, g_pan);

    const size_t PSZ = (size_t)CIN * MDIM;

    step_kernel<<<NBLOCKS, 256>>>(L, x,             pan + 0 * PSZ);
    step_kernel<<<NBLOCKS, 256>>>(L, pan + 0 * PSZ, pan + 1 * PSZ);
    step_kernel<<<NBLOCKS, 256>>>(L, pan + 1 * PSZ, pan + 2 * PSZ);
    step_kernel<<<NBLOCKS, 256>>>(L, pan + 2 * PSZ, pan + 3 * PSZ);

    mix_kernel<<<(MDIM + 255) / 256, 256>>>(x, theta, bias, out);
}

// round 8
// speedup vs baseline: 1.3726x; 1.3726x over previous
#include <cuda_runtime.h>
#include <cstdint>

#define MDIM 12288
#define CIN 8
#define NPAIR 4
#define COUT 16
#define KTAP 5

#define RPW 7                    // rows per consumer warp
#define NWC 4                    // consumer warps
#define RPB (RPW * NWC)          // 28 rows per CTA
#define NCTHR (NWC * 32)         // 128 consumer threads
#define NTHR (NCTHR + 32)        // +1 producer warp = 160
#define GRID 439                 // ceil(12288/28); 439*28 = 12292 (4 pad rows)

#define SCOLS 128                // columns per ring stage
#define NS 4                     // ring depth (== stages per panel tile)
#define NSTG (MDIM / SCOLS)      // 96
#define STAGE_B (RPB * SCOLS * 4)    // 14336 B
#define TJ 512                   // panel tile columns
#define PBUF_B (TJ * CIN * 4)    // 16384 B

#define SM_FULL  0               // 4 mbarriers (8B each)
#define SM_EMPTY 64
#define SM_PANEL 128
#define SM_RING  (SM_PANEL + PBUF_B)            // 16512
#define SMEM_TOTAL (SM_RING + NS * STAGE_B)     // 73856 B -> 3 CTAs/SM

#define SWZ(b) ((b) ^ (((b) >> 3) & 0x70))

__device__ __align__(16) float g_pan[KTAP - 1][CIN * MDIM];

// ---------- helpers ----------
__device__ __forceinline__ uint32_t smem_u32(const void* p) {
    uint32_t a;
    asm("{ .reg .u64 t; cvta.to.shared.u64 t, %1; cvt.u32.u64 %0, t; }" : "=r"(a) : "l"(p));
    return a;
}
__device__ __forceinline__ unsigned long long pack2(float lo, float hi) {
    unsigned long long r;
    asm("mov.b64 %0, {%1, %2};" : "=l"(r) : "f"(lo), "f"(hi));
    return r;
}
__device__ __forceinline__ void unpack2(unsigned long long v, float& lo, float& hi) {
    asm("mov.b64 {%0, %1}, %2;" : "=f"(lo), "=f"(hi) : "l"(v));
}
__device__ __forceinline__ void fma2(unsigned long long& acc,
                                     unsigned long long a, unsigned long long b) {
    asm("fma.rn.f32x2 %0, %1, %2, %0;" : "+l"(acc) : "l"(a), "l"(b));
}
__device__ __forceinline__ void cp16(uint32_t dst, const void* src) {
    asm volatile("cp.async.cg.shared.global [%0], [%1], 16;" :: "r"(dst), "l"(src) : "memory");
}
__device__ __forceinline__ void cp_commit() {
    asm volatile("cp.async.commit_group;" ::: "memory");
}
template <int N>
__device__ __forceinline__ void cp_wait() {
    asm volatile("cp.async.wait_group %0;" :: "n"(N) : "memory");
}
__device__ __forceinline__ void sts64(uint32_t a, unsigned long long v) {
    asm volatile("st.shared.b64 [%0], %1;" :: "r"(a), "l"(v) : "memory");
}
__device__ __forceinline__ void mbar_init(uint32_t a, uint32_t cnt) {
    asm volatile("mbarrier.init.shared.b64 [%0], %1;" :: "r"(a), "r"(cnt) : "memory");
}
__device__ __forceinline__ void mbar_arrive(uint32_t a) {
    asm volatile("mbarrier.arrive.release.cta.shared::cta.b64 _, [%0];" :: "r"(a) : "memory");
}
__device__ __forceinline__ void mbar_wait_acq(uint32_t a, uint32_t ph) {
    asm volatile(
        "{\n\t.reg .pred P;\n\t"
        "WL%=:\n\t"
        "mbarrier.try_wait.parity.acquire.cta.shared::cta.b64 P, [%0], %1, 0x989680;\n\t"
        "@P bra.uni WD%=;\n\t"
        "bra.uni WL%=;\n\t"
        "WD%=:\n\t}"
        :: "r"(a), "r"(ph) : "memory");
}

// next[i][m] = sum_j L[m][j] * cur[i][j]
__global__ __launch_bounds__(NTHR, 3)
void step_kernel(const float* __restrict__ L,
                 const float* __restrict__ cur,
                 float* __restrict__ nxt) {
    extern __shared__ __align__(128) unsigned char dsm[];
    const uint32_t smb = smem_u32(dsm);
    const int tid  = threadIdx.x;
    const int lane = tid & 31;
    const int w    = tid >> 5;
    const int m0   = blockIdx.x * RPB;

    if (tid == 0) {
#pragma unroll
        for (int s = 0; s < NS; ++s) {
            mbar_init(smb + SM_FULL  + 8 * s, 32);   // producer: 32 lane arrivals
            mbar_init(smb + SM_EMPTY + 8 * s, NWC);  // consumers: 1 arrive per warp
        }
    }
    __syncthreads();

    if (w == NWC) {
        // ================= producer warp =================
        int eph = 1;                                  // fresh-empty passes immediately
        for (int t = 0; t < NSTG; ++t) {
            const int slot = t & (NS - 1);
            mbar_wait_acq(smb + SM_EMPTY + 8 * slot, (uint32_t)eph);
            const uint32_t dst0 = smb + SM_RING + slot * STAGE_B + lane * 16;
            const int jb = t * SCOLS;
#pragma unroll
            for (int r = 0; r < RPB; ++r) {
                int mr = m0 + r; if (mr > MDIM - 1) mr = MDIM - 1;   // pad-row clamp
                cp16(dst0 + r * (SCOLS * 4),
                     L + (size_t)mr * MDIM + jb + lane * 4);
            }
            cp_commit();
            if (t >= 2) {                             // group t-2 retired -> publish
                cp_wait<2>();
                mbar_arrive(smb + SM_FULL + 8 * ((t - 2) & (NS - 1)));
            }
            if (slot == NS - 1) eph ^= 1;
        }
        cp_wait<1>();
        mbar_arrive(smb + SM_FULL + 8 * ((NSTG - 2) & (NS - 1)));
        cp_wait<0>();
        mbar_arrive(smb + SM_FULL + 8 * ((NSTG - 1) & (NS - 1)));
        return;
    }

    // ================= consumer warps =================
    const int r0 = w * RPW;

    unsigned long long acc[RPW][NPAIR];
#pragma unroll
    for (int r = 0; r < RPW; ++r)
#pragma unroll
        for (int p = 0; p < NPAIR; ++p) acc[r][p] = 0ull;

    int fph = 0;
    for (int t = 0; t < NSTG; ++t) {
        const int slot = t & (NS - 1);

        if (slot == 0) {
            // stage panel tile t/4 (all consumer warps past stages t-4..t-1)
            asm volatile("bar.sync 1, %0;" :: "n"(NCTHR) : "memory");
            const int jb = (t >> 2) * TJ;
#pragma unroll
            for (int q = 0; q < (TJ * NPAIR) / NCTHR; ++q) {   // 16 iters
                int idx = q * NCTHR + tid;                     // 0..2047
                int j   = idx & (TJ - 1);
                int p   = idx >> 9;                            // 0..3
                sts64(smb + SM_PANEL + SWZ(j * 32 + p * 8),
                      pack2(cur[(size_t)(2 * p) * MDIM + jb + j],
                            cur[(size_t)(2 * p + 1) * MDIM + jb + j]));
            }
            asm volatile("bar.sync 1, %0;" :: "n"(NCTHR) : "memory");
        }

        mbar_wait_acq(smb + SM_FULL + 8 * slot, (uint32_t)fph);

        const unsigned char* lb = dsm + SM_RING + slot * STAGE_B;
        float4 a[RPW];
#pragma unroll
        for (int r = 0; r < RPW; ++r)
            a[r] = *reinterpret_cast<const float4*>(
                       lb + (r0 + r) * (SCOLS * 4) + lane * 16);

        const unsigned char* pbp = dsm + SM_PANEL;
        const int jt0 = slot * SCOLS + 4 * lane;       // tile-local base col
#pragma unroll
        for (int jj = 0; jj < 4; ++jj) {
            const int jt = jt0 + jj;
            ulonglong2 q0 = *reinterpret_cast<const ulonglong2*>(pbp + SWZ(jt * 32));
            ulonglong2 q1 = *reinterpret_cast<const ulonglong2*>(pbp + SWZ(jt * 32 + 16));
#pragma unroll
            for (int r = 0; r < RPW; ++r) {
                float av = (jj == 0) ? a[r].x : (jj == 1) ? a[r].y
                         : (jj == 2) ? a[r].z : a[r].w;
                unsigned long long aa = pack2(av, av);
                fma2(acc[r][0], aa, q0.x);
                fma2(acc[r][1], aa, q0.y);
                fma2(acc[r][2], aa, q1.x);
                fma2(acc[r][3], aa, q1.y);
            }
        }

        if (lane == 0) mbar_arrive(smb + SM_EMPTY + 8 * slot);
        if (slot == NS - 1) fph ^= 1;
    }

    // warp reduction over lanes (disjoint j), then store
#pragma unroll
    for (int r = 0; r < RPW; ++r) {
        const int m = m0 + r0 + r;
#pragma unroll
        for (int p = 0; p < NPAIR; ++p) {
            float v0, v1;
            unpack2(acc[r][p], v0, v1);
#pragma unroll
            for (int d = 16; d > 0; d >>= 1) {
                v0 += __shfl_down_sync(0xffffffffu, v0, d);
                v1 += __shfl_down_sync(0xffffffffu, v1, d);
            }
            if (lane == 0 && m < MDIM) {
                nxt[(size_t)(2 * p) * MDIM + m]     = v0;
                nxt[(size_t)(2 * p + 1) * MDIM + m] = v1;
            }
        }
    }
}

// y[o][m] = bias[o] + sum_{i,k} theta[o][i][k] * P[k][i][m]
__global__ __launch_bounds__(256)
void mix_kernel(const float* __restrict__ x,
                const float* __restrict__ theta,
                const float* __restrict__ bias,
                float* __restrict__ out) {
    __shared__ float th[COUT * CIN * KTAP];
    __shared__ float bs[COUT];
    const int tid = threadIdx.x;
    for (int idx = tid; idx < COUT * CIN * KTAP; idx += blockDim.x)
        th[idx] = theta[idx];
    if (tid < COUT) bs[tid] = bias[tid];
    __syncthreads();

    const int m = blockIdx.x * blockDim.x + tid;
    if (m >= MDIM) return;

    float p[KTAP][CIN];
#pragma unroll
    for (int i = 0; i < CIN; ++i) p[0][i] = x[(size_t)i * MDIM + m];
#pragma unroll
    for (int k = 1; k < KTAP; ++k)
#pragma unroll
        for (int i = 0; i < CIN; ++i)
            p[k][i] = g_pan[k - 1][i * MDIM + m];

#pragma unroll
    for (int o = 0; o < COUT; ++o) {
        float s = bs[o];
#pragma unroll
        for (int i = 0; i < CIN; ++i)
#pragma unroll
            for (int k = 0; k < KTAP; ++k)
                s += th[(o * CIN + i) * KTAP + k] * p[k][i];
        out[(size_t)o * MDIM + m] = s;
    }
}

extern "C" void kernel_launch(void* const* d_in, const int* in_sizes, int n_in,
                              void* d_out, int out_size) {
    const float* L     = (const float*)d_in[0];
    const float* x     = (const float*)d_in[1];
    const float* theta = (const float*)d_in[2];
    const float* bias  = (const float*)d_in[3];
    float* out = (float*)d_out;

    cudaFuncSetAttribute(step_kernel,
                         cudaFuncAttributeMaxDynamicSharedMemorySize, SMEM_TOTAL);

    float* pan = nullptr;
    cudaGetSymbolAddress((void**)&pan, g_pan);

    const size_t PSZ = (size_t)CIN * MDIM;

    step_kernel<<<GRID, NTHR, SMEM_TOTAL>>>(L, x,             pan + 0 * PSZ);
    step_kernel<<<GRID, NTHR, SMEM_TOTAL>>>(L, pan + 0 * PSZ, pan + 1 * PSZ);
    step_kernel<<<GRID, NTHR, SMEM_TOTAL>>>(L, pan + 1 * PSZ, pan + 2 * PSZ);
    step_kernel<<<GRID, NTHR, SMEM_TOTAL>>>(L, pan + 2 * PSZ, pan + 3 * PSZ);

    mix_kernel<<<(MDIM + 255) / 256, 256>>>(x, theta, bias, out);
}

// round 9
// speedup vs baseline: 1.4512x; 1.0573x over previous
#include <cuda_runtime.h>
#include <cstdint>

#define MDIM 12288
#define CIN 8
#define NPAIR 4
#define COUT 16
#define KTAP 5

#define RPW 7                    // rows per consumer warp
#define NWC 4                    // consumer warps
#define RPB (RPW * NWC)          // 28 rows per CTA
#define NCTHR (NWC * 32)         // 128 consumer threads
#define NTHR (NCTHR + 32)        // +1 producer warp = 160
#define GRID 439                 // ceil(12288/28)

#define SCOLS 128                // columns per ring stage
#define NS 4                     // ring depth
#define NSTG (MDIM / SCOLS)      // 96
#define STAGE_L (RPB * SCOLS * 4)    // 14336 B  (L rows chunk)
#define STAGE_P (SCOLS * CIN * 4)    // 4096 B   (panel chunk, swizzled pair-packed)
#define STAGE_B (STAGE_L + STAGE_P)  // 18432 B

#define SM_FULL  0               // 4 mbarriers (8B each)
#define SM_EMPTY 64
#define SM_RING  128
#define SMEM_TOTAL (SM_RING + NS * STAGE_B)   // 73856 B -> 3 CTAs/SM

#define SWZ(b) ((b) ^ (((b) >> 3) & 0x70))

// Panels in column-major [M][CIN] layout (8 floats contiguous per m).
__device__ __align__(16) float g_pan[KTAP - 1][MDIM * CIN];
__device__ __align__(16) float g_xT[MDIM * CIN];

// ---------- helpers ----------
__device__ __forceinline__ uint32_t smem_u32(const void* p) {
    uint32_t a;
    asm("{ .reg .u64 t; cvta.to.shared.u64 t, %1; cvt.u32.u64 %0, t; }" : "=r"(a) : "l"(p));
    return a;
}
__device__ __forceinline__ unsigned long long pack2(float lo, float hi) {
    unsigned long long r;
    asm("mov.b64 %0, {%1, %2};" : "=l"(r) : "f"(lo), "f"(hi));
    return r;
}
__device__ __forceinline__ void unpack2(unsigned long long v, float& lo, float& hi) {
    asm("mov.b64 {%0, %1}, %2;" : "=f"(lo), "=f"(hi) : "l"(v));
}
__device__ __forceinline__ void fma2(unsigned long long& acc,
                                     unsigned long long a, unsigned long long b) {
    asm("fma.rn.f32x2 %0, %1, %2, %0;" : "+l"(acc) : "l"(a), "l"(b));
}
__device__ __forceinline__ void cp16(uint32_t dst, const void* src) {
    asm volatile("cp.async.cg.shared.global [%0], [%1], 16;" :: "r"(dst), "l"(src) : "memory");
}
__device__ __forceinline__ void cp_commit() {
    asm volatile("cp.async.commit_group;" ::: "memory");
}
template <int N>
__device__ __forceinline__ void cp_wait() {
    asm volatile("cp.async.wait_group %0;" :: "n"(N) : "memory");
}
__device__ __forceinline__ void mbar_init(uint32_t a, uint32_t cnt) {
    asm volatile("mbarrier.init.shared.b64 [%0], %1;" :: "r"(a), "r"(cnt) : "memory");
}
__device__ __forceinline__ void mbar_arrive(uint32_t a) {
    asm volatile("mbarrier.arrive.release.cta.shared::cta.b64 _, [%0];" :: "r"(a) : "memory");
}
__device__ __forceinline__ void mbar_wait_acq(uint32_t a, uint32_t ph) {
    asm volatile(
        "{\n\t.reg .pred P;\n\t"
        "WL%=:\n\t"
        "mbarrier.try_wait.parity.acquire.cta.shared::cta.b64 P, [%0], %1, 0x989680;\n\t"
        "@P bra.uni WD%=;\n\t"
        "bra.uni WL%=;\n\t"
        "WD%=:\n\t}"
        :: "r"(a), "r"(ph) : "memory");
}

// xT[m*8 + i] = x[i*M + m]
__global__ __launch_bounds__(256)
void transpose_kernel(const float* __restrict__ x, float* __restrict__ xT) {
    const int m = blockIdx.x * blockDim.x + threadIdx.x;
    if (m >= MDIM) return;
    float v[CIN];
#pragma unroll
    for (int i = 0; i < CIN; ++i) v[i] = x[(size_t)i * MDIM + m];
    float4* dst = reinterpret_cast<float4*>(xT + (size_t)m * CIN);
    dst[0] = make_float4(v[0], v[1], v[2], v[3]);
    dst[1] = make_float4(v[4], v[5], v[6], v[7]);
}

// nxt[m][i] = sum_j L[m][j] * cur[j][i]   (cur, nxt column-major [M][CIN])
__global__ __launch_bounds__(NTHR, 3)
void step_kernel(const float* __restrict__ L,
                 const float* __restrict__ cur,
                 float* __restrict__ nxt) {
    extern __shared__ __align__(128) unsigned char dsm[];
    const uint32_t smb = smem_u32(dsm);
    const int tid  = threadIdx.x;
    const int lane = tid & 31;
    const int w    = tid >> 5;
    const int m0   = blockIdx.x * RPB;

    if (tid == 0) {
#pragma unroll
        for (int s = 0; s < NS; ++s) {
            mbar_init(smb + SM_FULL  + 8 * s, 32);   // 32 producer-lane arrivals
            mbar_init(smb + SM_EMPTY + 8 * s, NWC);  // 1 arrive per consumer warp
        }
    }
    __syncthreads();

    if (w == NWC) {
        // ================= producer warp =================
        const unsigned char* curb = reinterpret_cast<const unsigned char*>(cur);
        int eph = 1;                                  // fresh-empty passes immediately
        for (int t = 0; t < NSTG; ++t) {
            const int slot = t & (NS - 1);
            mbar_wait_acq(smb + SM_EMPTY + 8 * slot, (uint32_t)eph);
            const uint32_t dst0 = smb + SM_RING + slot * STAGE_B;
            const int jb = t * SCOLS;
            // L rows chunk: 28 rows x 512 B (lane covers 16 B of each row)
#pragma unroll
            for (int r = 0; r < RPB; ++r) {
                int mr = m0 + r; if (mr > MDIM - 1) mr = MDIM - 1;   // pad-row clamp
                cp16(dst0 + r * (SCOLS * 4) + lane * 16,
                     L + (size_t)mr * MDIM + jb + lane * 4);
            }
            // panel chunk: 128 cols x 32 B, contiguous src, swizzled dst
#pragma unroll
            for (int q = 0; q < 8; ++q) {
                const uint32_t off = (uint32_t)(lane * 16 + q * 512);
                cp16(dst0 + STAGE_L + SWZ(off),
                     curb + (size_t)jb * 32 + off);
            }
            cp_commit();
            if (t >= 2) {                             // group t-2 retired -> publish
                cp_wait<2>();
                mbar_arrive(smb + SM_FULL + 8 * ((t - 2) & (NS - 1)));
            }
            if (slot == NS - 1) eph ^= 1;
        }
        cp_wait<1>();
        mbar_arrive(smb + SM_FULL + 8 * ((NSTG - 2) & (NS - 1)));
        cp_wait<0>();
        mbar_arrive(smb + SM_FULL + 8 * ((NSTG - 1) & (NS - 1)));
        return;
    }

    // ================= consumer warps =================
    const int r0 = w * RPW;

    unsigned long long acc[RPW][NPAIR];
#pragma unroll
    for (int r = 0; r < RPW; ++r)
#pragma unroll
        for (int p = 0; p < NPAIR; ++p) acc[r][p] = 0ull;

    int fph = 0;
    for (int t = 0; t < NSTG; ++t) {
        const int slot = t & (NS - 1);
        mbar_wait_acq(smb + SM_FULL + 8 * slot, (uint32_t)fph);

        const unsigned char* lb = dsm + SM_RING + slot * STAGE_B;
        float4 a[RPW];
#pragma unroll
        for (int r = 0; r < RPW; ++r)
            a[r] = *reinterpret_cast<const float4*>(
                       lb + (r0 + r) * (SCOLS * 4) + lane * 16);

        const unsigned char* pbp = lb + STAGE_L;
#pragma unroll
        for (int jj = 0; jj < 4; ++jj) {
            const int jl = 4 * lane + jj;              // stage-local column
            ulonglong2 q0 = *reinterpret_cast<const ulonglong2*>(pbp + SWZ(jl * 32));
            ulonglong2 q1 = *reinterpret_cast<const ulonglong2*>(pbp + SWZ(jl * 32 + 16));
#pragma unroll
            for (int r = 0; r < RPW; ++r) {
                float av = (jj == 0) ? a[r].x : (jj == 1) ? a[r].y
                         : (jj == 2) ? a[r].z : a[r].w;
                unsigned long long aa = pack2(av, av);
                fma2(acc[r][0], aa, q0.x);
                fma2(acc[r][1], aa, q0.y);
                fma2(acc[r][2], aa, q1.x);
                fma2(acc[r][3], aa, q1.y);
            }
        }

        if (lane == 0) mbar_arrive(smb + SM_EMPTY + 8 * slot);
        if (slot == NS - 1) fph ^= 1;
    }

    // warp reduction over lanes (disjoint j), then store (column-major out)
#pragma unroll
    for (int r = 0; r < RPW; ++r) {
        const int m = m0 + r0 + r;
        float ov[CIN];
#pragma unroll
        for (int p = 0; p < NPAIR; ++p) {
            float v0, v1;
            unpack2(acc[r][p], v0, v1);
#pragma unroll
            for (int d = 16; d > 0; d >>= 1) {
                v0 += __shfl_down_sync(0xffffffffu, v0, d);
                v1 += __shfl_down_sync(0xffffffffu, v1, d);
            }
            ov[2 * p] = v0; ov[2 * p + 1] = v1;
        }
        if (lane == 0 && m < MDIM) {
            float4* dst = reinterpret_cast<float4*>(nxt + (size_t)m * CIN);
            dst[0] = make_float4(ov[0], ov[1], ov[2], ov[3]);
            dst[1] = make_float4(ov[4], ov[5], ov[6], ov[7]);
        }
    }
}

// y[o][m] = bias[o] + sum_{i,k} theta[o][i][k] * P[k][m][i]
__global__ __launch_bounds__(256)
void mix_kernel(const float* __restrict__ x,
                const float* __restrict__ theta,
                const float* __restrict__ bias,
                float* __restrict__ out) {
    __shared__ float th[COUT * CIN * KTAP];
    __shared__ float bs[COUT];
    const int tid = threadIdx.x;
    for (int idx = tid; idx < COUT * CIN * KTAP; idx += blockDim.x)
        th[idx] = theta[idx];
    if (tid < COUT) bs[tid] = bias[tid];
    __syncthreads();

    const int m = blockIdx.x * blockDim.x + tid;
    if (m >= MDIM) return;

    float p[KTAP][CIN];
#pragma unroll
    for (int i = 0; i < CIN; ++i) p[0][i] = x[(size_t)i * MDIM + m];
#pragma unroll
    for (int k = 1; k < KTAP; ++k) {
        const float4* src = reinterpret_cast<const float4*>(
                                &g_pan[k - 1][(size_t)m * CIN]);
        float4 lo = src[0], hi = src[1];
        p[k][0] = lo.x; p[k][1] = lo.y; p[k][2] = lo.z; p[k][3] = lo.w;
        p[k][4] = hi.x; p[k][5] = hi.y; p[k][6] = hi.z; p[k][7] = hi.w;
    }

#pragma unroll
    for (int o = 0; o < COUT; ++o) {
        float s = bs[o];
#pragma unroll
        for (int i = 0; i < CIN; ++i)
#pragma unroll
            for (int k = 0; k < KTAP; ++k)
                s += th[(o * CIN + i) * KTAP + k] * p[k][i];
        out[(size_t)o * MDIM + m] = s;
    }
}

extern "C" void kernel_launch(void* const* d_in, const int* in_sizes, int n_in,
                              void* d_out, int out_size) {
    const float* L     = (const float*)d_in[0];
    const float* x     = (const float*)d_in[1];
    const float* theta = (const float*)d_in[2];
    const float* bias  = (const float*)d_in[3];
    float* out = (float*)d_out;

    cudaFuncSetAttribute(step_kernel,
                         cudaFuncAttributeMaxDynamicSharedMemorySize, SMEM_TOTAL);

    float* pan = nullptr;
    cudaGetSymbolAddress((void**)&pan, g_pan);
    float* xT = nullptr;
    cudaGetSymbolAddress((void**)&xT, g_xT);

    const size_t PSZ = (size_t)MDIM * CIN;

    transpose_kernel<<<(MDIM + 255) / 256, 256>>>(x, xT);
    step_kernel<<<GRID, NTHR, SMEM_TOTAL>>>(L, xT,            pan + 0 * PSZ);
    step_kernel<<<GRID, NTHR, SMEM_TOTAL>>>(L, pan + 0 * PSZ, pan + 1 * PSZ);
    step_kernel<<<GRID, NTHR, SMEM_TOTAL>>>(L, pan + 1 * PSZ, pan + 2 * PSZ);
    step_kernel<<<GRID, NTHR, SMEM_TOTAL>>>(L, pan + 2 * PSZ, pan + 3 * PSZ);

    mix_kernel<<<(MDIM + 255) / 256, 256>>>(x, theta, bias, out);
}

// round 11
// speedup vs baseline: 1.5464x; 1.0656x over previous
#include <cuda_runtime.h>
#include <cstdint>

#define MDIM 12288
#define CIN 8
#define NPAIR 4
#define COUT 16
#define KTAP 5

#define RPW 7                    // rows per consumer warp
#define NWC 4                    // consumer warps
#define RPB (RPW * NWC)          // 28 rows per CTA
#define NCTHR (NWC * 32)         // 128 consumer threads
#define NTHR (NCTHR + 32)        // +1 producer warp = 160
#define GRID 439                 // ceil(12288/28)

#define SCOLS 128                // columns per ring stage
#define NS 4                     // ring depth
#define NSTG (MDIM / SCOLS)      // 96
#define STAGE_L (RPB * SCOLS * 4)    // 14336 B  (L rows chunk)
#define STAGE_P (SCOLS * CIN * 4)    // 4096 B   (panel chunk, swizzled pair-packed)
#define STAGE_B (STAGE_L + STAGE_P)  // 18432 B

#define SM_FULL  0               // 4 mbarriers (8B each)
#define SM_EMPTY 64
#define SM_RING  128
#define SMEM_TOTAL (SM_RING + NS * STAGE_B)   // 73856 B -> 3 CTAs/SM

#define SWZ(b) ((b) ^ (((b) >> 3) & 0x70))

// Panels in column-major [M][CIN] layout (8 floats contiguous per m).
__device__ __align__(16) float g_pan[KTAP - 1][MDIM * CIN];
__device__ __align__(16) float g_xT[MDIM * CIN];

// ---------- helpers ----------
__device__ __forceinline__ uint32_t smem_u32(const void* p) {
    uint32_t a;
    asm("{ .reg .u64 t; cvta.to.shared.u64 t, %1; cvt.u32.u64 %0, t; }" : "=r"(a) : "l"(p));
    return a;
}
__device__ __forceinline__ unsigned long long pack2(float lo, float hi) {
    unsigned long long r;
    asm("mov.b64 %0, {%1, %2};" : "=l"(r) : "f"(lo), "f"(hi));
    return r;
}
__device__ __forceinline__ void unpack2(unsigned long long v, float& lo, float& hi) {
    asm("mov.b64 {%0, %1}, %2;" : "=f"(lo), "=f"(hi) : "l"(v));
}
__device__ __forceinline__ void fma2(unsigned long long& acc,
                                     unsigned long long a, unsigned long long b) {
    asm("fma.rn.f32x2 %0, %1, %2, %0;" : "+l"(acc) : "l"(a), "l"(b));
}
__device__ __forceinline__ void cp16(uint32_t dst, const void* src) {
    asm volatile("cp.async.cg.shared.global [%0], [%1], 16;" :: "r"(dst), "l"(src) : "memory");
}
__device__ __forceinline__ void cp_commit() {
    asm volatile("cp.async.commit_group;" ::: "memory");
}
template <int N>
__device__ __forceinline__ void cp_wait() {
    asm volatile("cp.async.wait_group %0;" :: "n"(N) : "memory");
}
__device__ __forceinline__ void mbar_init(uint32_t a, uint32_t cnt) {
    asm volatile("mbarrier.init.shared.b64 [%0], %1;" :: "r"(a), "r"(cnt) : "memory");
}
__device__ __forceinline__ void mbar_arrive(uint32_t a) {
    asm volatile("mbarrier.arrive.release.cta.shared::cta.b64 _, [%0];" :: "r"(a) : "memory");
}
__device__ __forceinline__ void mbar_wait_acq(uint32_t a, uint32_t ph) {
    asm volatile(
        "{\n\t.reg .pred P;\n\t"
        "WL%=:\n\t"
        "mbarrier.try_wait.parity.acquire.cta.shared::cta.b64 P, [%0], %1, 0x989680;\n\t"
        "@P bra.uni WD%=;\n\t"
        "bra.uni WL%=;\n\t"
        "WD%=:\n\t}"
        :: "r"(a), "r"(ph) : "memory");
}

// xT[m*8 + i] = x[i*M + m]
__global__ __launch_bounds__(256)
void transpose_kernel(const float* __restrict__ x, float* __restrict__ xT) {
    const int m = blockIdx.x * blockDim.x + threadIdx.x;
    if (m >= MDIM) return;
    float v[CIN];
#pragma unroll
    for (int i = 0; i < CIN; ++i) v[i] = x[(size_t)i * MDIM + m];
    float4* dst = reinterpret_cast<float4*>(xT + (size_t)m * CIN);
    dst[0] = make_float4(v[0], v[1], v[2], v[3]);
    dst[1] = make_float4(v[4], v[5], v[6], v[7]);
}

// nxt[m][i] = sum_j L[m][j] * cur[j][i]   (cur, nxt column-major [M][CIN])
// dir=0: columns ascending; dir=1: descending (serpentine across launches so
// each step's first reads hit the L2 residue left by the previous step).
__global__ __launch_bounds__(NTHR, 3)
void step_kernel(const float* __restrict__ L,
                 const float* __restrict__ cur,
                 float* __restrict__ nxt,
                 int dir) {
    extern __shared__ __align__(128) unsigned char dsm[];
    const uint32_t smb = smem_u32(dsm);
    const int tid  = threadIdx.x;
    const int lane = tid & 31;
    const int w    = tid >> 5;
    const int m0   = blockIdx.x * RPB;

    if (tid == 0) {
#pragma unroll
        for (int s = 0; s < NS; ++s) {
            mbar_init(smb + SM_FULL  + 8 * s, 32);   // 32 producer-lane arrivals
            mbar_init(smb + SM_EMPTY + 8 * s, NWC);  // 1 arrive per consumer warp
        }
    }
    __syncthreads();

    if (w == NWC) {
        // ================= producer warp =================
        const unsigned char* curb = reinterpret_cast<const unsigned char*>(cur);
        int eph = 1;                                  // fresh-empty passes immediately
        for (int u = 0; u < NSTG; ++u) {
            const int t    = dir ? (NSTG - 1 - u) : u;   // data stage
            const int slot = u & (NS - 1);               // ring slot
            mbar_wait_acq(smb + SM_EMPTY + 8 * slot, (uint32_t)eph);
            const uint32_t dst0 = smb + SM_RING + slot * STAGE_B;
            const int jb = t * SCOLS;
            // L rows chunk: 28 rows x 512 B (lane covers 16 B of each row)
#pragma unroll
            for (int r = 0; r < RPB; ++r) {
                int mr = m0 + r; if (mr > MDIM - 1) mr = MDIM - 1;   // pad-row clamp
                cp16(dst0 + r * (SCOLS * 4) + lane * 16,
                     L + (size_t)mr * MDIM + jb + lane * 4);
            }
            // panel chunk: 128 cols x 32 B, contiguous src, swizzled dst
#pragma unroll
            for (int q = 0; q < 8; ++q) {
                const uint32_t off = (uint32_t)(lane * 16 + q * 512);
                cp16(dst0 + STAGE_L + SWZ(off),
                     curb + (size_t)jb * 32 + off);
            }
            cp_commit();
            if (u >= 2) {                             // group u-2 retired -> publish
                cp_wait<2>();
                mbar_arrive(smb + SM_FULL + 8 * ((u - 2) & (NS - 1)));
            }
            if (slot == NS - 1) eph ^= 1;
        }
        cp_wait<1>();
        mbar_arrive(smb + SM_FULL + 8 * ((NSTG - 2) & (NS - 1)));
        cp_wait<0>();
        mbar_arrive(smb + SM_FULL + 8 * ((NSTG - 1) & (NS - 1)));
        return;
    }

    // ================= consumer warps =================
    const int r0 = w * RPW;

    unsigned long long acc[RPW][NPAIR];
#pragma unroll
    for (int r = 0; r < RPW; ++r)
#pragma unroll
        for (int p = 0; p < NPAIR; ++p) acc[r][p] = 0ull;

    int fph = 0;
    for (int u = 0; u < NSTG; ++u) {
        const int slot = u & (NS - 1);
        mbar_wait_acq(smb + SM_FULL + 8 * slot, (uint32_t)fph);

        const unsigned char* lb = dsm + SM_RING + slot * STAGE_B;
        float4 a[RPW];
#pragma unroll
        for (int r = 0; r < RPW; ++r)
            a[r] = *reinterpret_cast<const float4*>(
                       lb + (r0 + r) * (SCOLS * 4) + lane * 16);

        const unsigned char* pbp = lb + STAGE_L;
#pragma unroll
        for (int jj = 0; jj < 4; ++jj) {
            const int jl = 4 * lane + jj;              // stage-local column
            ulonglong2 q0 = *reinterpret_cast<const ulonglong2*>(pbp + SWZ(jl * 32));
            ulonglong2 q1 = *reinterpret_cast<const ulonglong2*>(pbp + SWZ(jl * 32 + 16));
#pragma unroll
            for (int r = 0; r < RPW; ++r) {
                float av = (jj == 0) ? a[r].x : (jj == 1) ? a[r].y
                         : (jj == 2) ? a[r].z : a[r].w;
                unsigned long long aa = pack2(av, av);
                fma2(acc[r][0], aa, q0.x);
                fma2(acc[r][1], aa, q0.y);
                fma2(acc[r][2], aa, q1.x);
                fma2(acc[r][3], aa, q1.y);
            }
        }

        if (lane == 0) mbar_arrive(smb + SM_EMPTY + 8 * slot);
        if (slot == NS - 1) fph ^= 1;
    }

    // warp reduction over lanes (disjoint j), then store (column-major out)
#pragma unroll
    for (int r = 0; r < RPW; ++r) {
        const int m = m0 + r0 + r;
        float ov[CIN];
#pragma unroll
        for (int p = 0; p < NPAIR; ++p) {
            float v0, v1;
            unpack2(acc[r][p], v0, v1);
#pragma unroll
            for (int d = 16; d > 0; d >>= 1) {
                v0 += __shfl_down_sync(0xffffffffu, v0, d);
                v1 += __shfl_down_sync(0xffffffffu, v1, d);
            }
            ov[2 * p] = v0; ov[2 * p + 1] = v1;
        }
        if (lane == 0 && m < MDIM) {
            float4* dst = reinterpret_cast<float4*>(nxt + (size_t)m * CIN);
            dst[0] = make_float4(ov[0], ov[1], ov[2], ov[3]);
            dst[1] = make_float4(ov[4], ov[5], ov[6], ov[7]);
        }
    }
}

// y[o][m] = bias[o] + sum_{i,k} theta[o][i][k] * P[k][m][i]
__global__ __launch_bounds__(256)
void mix_kernel(const float* __restrict__ x,
                const float* __restrict__ theta,
                const float* __restrict__ bias,
                float* __restrict__ out) {
    __shared__ float th[COUT * CIN * KTAP];
    __shared__ float bs[COUT];
    const int tid = threadIdx.x;
    for (int idx = tid; idx < COUT * CIN * KTAP; idx += blockDim.x)
        th[idx] = theta[idx];
    if (tid < COUT) bs[tid] = bias[tid];
    __syncthreads();

    const int m = blockIdx.x * blockDim.x + tid;
    if (m >= MDIM) return;

    float p[KTAP][CIN];
#pragma unroll
    for (int i = 0; i < CIN; ++i) p[0][i] = x[(size_t)i * MDIM + m];
#pragma unroll
    for (int k = 1; k < KTAP; ++k) {
        const float4* src = reinterpret_cast<const float4*>(
                                &g_pan[k - 1][(size_t)m * CIN]);
        float4 lo = src[0], hi = src[1];
        p[k][0] = lo.x; p[k][1] = lo.y; p[k][2] = lo.z; p[k][3] = lo.w;
        p[k][4] = hi.x; p[k][5] = hi.y; p[k][6] = hi.z; p[k][7] = hi.w;
    }

#pragma unroll
    for (int o = 0; o < COUT; ++o) {
        float s = bs[o];
#pragma unroll
        for (int i = 0; i < CIN; ++i)
#pragma unroll
            for (int k = 0; k < KTAP; ++k)
                s += th[(o * CIN + i) * KTAP + k] * p[k][i];
        out[(size_t)o * MDIM + m] = s;
    }
}

extern "C" void kernel_launch(void* const* d_in, const int* in_sizes, int n_in,
                              void* d_out, int out_size) {
    const float* L     = (const float*)d_in[0];
    const float* x     = (const float*)d_in[1];
    const float* theta = (const float*)d_in[2];
    const float* bias  = (const float*)d_in[3];
    float* out = (float*)d_out;

    cudaFuncSetAttribute(step_kernel,
                         cudaFuncAttributeMaxDynamicSharedMemorySize, SMEM_TOTAL);

    float* pan = nullptr;
    cudaGetSymbolAddress((void**)&pan, g_pan);
    float* xT = nullptr;
    cudaGetSymbolAddress((void**)&xT, g_xT);

    const size_t PSZ = (size_t)MDIM * CIN;

    transpose_kernel<<<(MDIM + 255) / 256, 256>>>(x, xT);
    // Serpentine direction: each step starts where the previous one ended
    // (including replay wrap: step 4 ends at low columns, step 1 starts there).
    step_kernel<<<GRID, NTHR, SMEM_TOTAL>>>(L, xT,            pan + 0 * PSZ, 0);
    step_kernel<<<GRID, NTHR, SMEM_TOTAL>>>(L, pan + 0 * PSZ, pan + 1 * PSZ, 1);
    step_kernel<<<GRID, NTHR, SMEM_TOTAL>>>(L, pan + 1 * PSZ, pan + 2 * PSZ, 0);
    step_kernel<<<GRID, NTHR, SMEM_TOTAL>>>(L, pan + 2 * PSZ, pan + 3 * PSZ, 1);

    mix_kernel<<<(MDIM + 255) / 256, 256>>>(x, theta, bias, out);
}